// round 16
// baseline (speedup 1.0000x reference)
#include <cuda_runtime.h>
#include <cstdint>

// PolynomialFeatures: out[b] = concat(x[b], x[b, idx_a] * x[b, idx_b])
// x: [B, 256] fp32, out: [B, 256+32640] fp32.
//
// v12: v11 compute core (analytic combination indices, feature-major float4
// smem so one LDS.128 serves 4 rows, interleaved conflict-free j-gather)
// but the crossed-region stores go through TMA BULK STORES instead of STG:
// each 1024-element chunk per row is computed into smem (STS.128) and
// drained by cp.async.bulk.global.shared::cta (4KB per row per chunk).
// Rationale: 4 structurally different STG kernels all pinned at DRAM~70%
// with nothing saturated -> limiter is the SM store path (store-queue depth
// vs L2 write latency). TMA has deep async queues and removes ~1M STG.128
// from the LSU. fence.proxy.async + wait_group 0 provide ordering.

#define ROWS_PER_BLOCK 4
#define F_FEAT 256
#define THREADS 256
#define NPAIRS_EXPECTED 32640   // 256*255/2
#define CHUNK 1024              // crossed elements per chunk per row
#define NCHUNKS 32              // ceil(32640/1024) = 32 (last = 896)

__device__ __forceinline__ int pbase(int i) {
    // start of run i: 255*i - i*(i-1)/2
    return i * 255 - ((i * (i - 1)) >> 1);
}
// interleave: consecutive-by-4 features land in adjacent float4 slots
__device__ __forceinline__ int il(int j) {
    return (j >> 2) + (j & 3) * 64;
}

__device__ __forceinline__ uint32_t smem_u32(const void* p) {
    uint32_t a;
    asm("{ .reg .u64 t; cvta.to.shared.u64 t, %1; cvt.u32.u64 %0, t; }"
        : "=r"(a) : "l"(p));
    return a;
}

__global__ __launch_bounds__(THREADS, 7)
void poly_features_v12(const float* __restrict__ x,
                       float*       __restrict__ out)
{
    __shared__ float4 sx4[F_FEAT];                    // 4 KB
    __shared__ __align__(16) float buf[ROWS_PER_BLOCK][CHUNK];  // 16 KB

    const int row0 = blockIdx.x * ROWS_PER_BLOCK;
    const int t    = threadIdx.x;
    const size_t ostride = (size_t)(F_FEAT + NPAIRS_EXPECTED);

    // Stage feature t for the 4 rows; copy x -> out[:, :F] directly.
    {
        const float v0 = x[(size_t)(row0 + 0) * F_FEAT + t];
        const float v1 = x[(size_t)(row0 + 1) * F_FEAT + t];
        const float v2 = x[(size_t)(row0 + 2) * F_FEAT + t];
        const float v3 = x[(size_t)(row0 + 3) * F_FEAT + t];
        out[(size_t)(row0 + 0) * ostride + t] = v0;
        out[(size_t)(row0 + 1) * ostride + t] = v1;
        out[(size_t)(row0 + 2) * ostride + t] = v2;
        out[(size_t)(row0 + 3) * ostride + t] = v3;
        sx4[il(t)] = make_float4(v0, v1, v2, v3);
    }
    __syncthreads();

    float* ob[ROWS_PER_BLOCK];
    #pragma unroll
    for (int r = 0; r < ROWS_PER_BLOCK; r++)
        ob[r] = out + (size_t)(row0 + r) * ostride + F_FEAT;

    for (int c = 0; c < NCHUNKS; c++) {
        const int p0  = c * CHUNK;
        const int len = min(CHUNK, NPAIRS_EXPECTED - p0);
        const int ng  = len >> 2;              // groups this chunk (256 or 224)

        if (t < ng) {
            const int p = p0 + (t << 2);

            // Run index guess + exact fixups, carrying bounds incrementally.
            int i = (int)((511.0f - sqrtf((float)(261121 - 8 * p))) * 0.5f);
            i = max(0, min(i, 254));
            int bi  = pbase(i);
            int bi1 = bi + (255 - i);
            while (bi1 <= p) { ++i; bi = bi1; bi1 += 255 - i; }
            while (i > 0 && bi > p) { bi1 = bi; --i; bi -= 255 - i; }

            float4 v0, v1, v2, v3;
            {   // e = 0
                const int j = p - bi + i + 1;
                const float4 a = sx4[il(i)];
                const float4 b = sx4[il(j)];
                v0.x = a.x * b.x; v1.x = a.y * b.y; v2.x = a.z * b.z; v3.x = a.w * b.w;
            }
            {   // e = 1
                const int pe = p + 1;
                while (pe >= bi1) { ++i; bi = bi1; bi1 += 255 - i; }
                const int j = pe - bi + i + 1;
                const float4 a = sx4[il(i)];
                const float4 b = sx4[il(j)];
                v0.y = a.x * b.x; v1.y = a.y * b.y; v2.y = a.z * b.z; v3.y = a.w * b.w;
            }
            {   // e = 2
                const int pe = p + 2;
                while (pe >= bi1) { ++i; bi = bi1; bi1 += 255 - i; }
                const int j = pe - bi + i + 1;
                const float4 a = sx4[il(i)];
                const float4 b = sx4[il(j)];
                v0.z = a.x * b.x; v1.z = a.y * b.y; v2.z = a.z * b.z; v3.z = a.w * b.w;
            }
            {   // e = 3
                const int pe = p + 3;
                while (pe >= bi1) { ++i; bi = bi1; bi1 += 255 - i; }
                const int j = pe - bi + i + 1;
                const float4 a = sx4[il(i)];
                const float4 b = sx4[il(j)];
                v0.w = a.x * b.x; v1.w = a.y * b.y; v2.w = a.z * b.z; v3.w = a.w * b.w;
            }

            const int lp = t << 2;     // local position in chunk
            *(float4*)&buf[0][lp] = v0;
            *(float4*)&buf[1][lp] = v1;
            *(float4*)&buf[2][lp] = v2;
            *(float4*)&buf[3][lp] = v3;
        }
        __syncthreads();               // all STS visible

        if (t == 0) {
            asm volatile("fence.proxy.async.shared::cta;" ::: "memory");
            const uint32_t bytes = (uint32_t)(len * 4);
            #pragma unroll
            for (int r = 0; r < ROWS_PER_BLOCK; r++) {
                const uint32_t src = smem_u32(&buf[r][0]);
                asm volatile(
                    "cp.async.bulk.global.shared::cta.bulk_group [%0], [%1], %2;"
                    :: "l"(ob[r] + p0), "r"(src), "r"(bytes) : "memory");
            }
            asm volatile("cp.async.bulk.commit_group;" ::: "memory");
            asm volatile("cp.async.bulk.wait_group 0;" ::: "memory");
        }
        __syncthreads();               // buffer free for next chunk
    }
}

// ---- Generic fallback (idx-driven), used if shapes don't fit fast path ----
__global__ __launch_bounds__(256)
void poly_features_generic(const float* __restrict__ x,
                           const int*   __restrict__ idx_a,
                           const int*   __restrict__ idx_b,
                           float*       __restrict__ out,
                           int B, int npairs)
{
    __shared__ float sxl[ROWS_PER_BLOCK][F_FEAT];
    const int row0 = blockIdx.x * ROWS_PER_BLOCK;
    const int tid  = threadIdx.x;
    const size_t out_stride = (size_t)(F_FEAT + npairs);

    #pragma unroll
    for (int r = 0; r < ROWS_PER_BLOCK; r++) {
        int row = row0 + r;
        if (row < B) {
            float v = x[(size_t)row * F_FEAT + tid];
            sxl[r][tid] = v;
            out[(size_t)row * out_stride + tid] = v;
        }
    }
    __syncthreads();

    const int rows_here = min(ROWS_PER_BLOCK, B - row0);
    for (int p = tid; p < npairs; p += 256) {
        int ai = idx_a[p];
        int bi = idx_b[p];
        #pragma unroll
        for (int r = 0; r < ROWS_PER_BLOCK; r++) {
            if (r < rows_here)
                out[(size_t)(row0 + r) * out_stride + F_FEAT + p] = sxl[r][ai] * sxl[r][bi];
        }
    }
}

extern "C" void kernel_launch(void* const* d_in, const int* in_sizes, int n_in,
                              void* d_out, int out_size)
{
    const float* x     = (const float*)d_in[0];
    const int*   idx_a = (const int*)d_in[1];
    const int*   idx_b = (const int*)d_in[2];
    float*       out   = (float*)d_out;

    const int B = in_sizes[0] / F_FEAT;
    const int npairs = in_sizes[1];

    if (npairs == NPAIRS_EXPECTED && (B % ROWS_PER_BLOCK) == 0) {
        const int grid = B / ROWS_PER_BLOCK;
        poly_features_v12<<<grid, THREADS>>>(x, out);
    } else {
        const int grid = (B + ROWS_PER_BLOCK - 1) / ROWS_PER_BLOCK;
        poly_features_generic<<<grid, 256>>>(x, idx_a, idx_b, out, B, npairs);
    }
}